// round 16
// baseline (speedup 1.0000x reference)
#include <cuda_runtime.h>
#include <cstdint>

#define BB 4
#define SS 4096
#define DD 2048
#define RR 4
#define RFF 16
#define NROWS (BB*SS)   // 16384
#define TRM 16          // rows per block in k_main
#define EPS 1e-6f
#define NB 24           // B columns: 0..3 wV, 4..7 U, 8..23 wW1

typedef unsigned long long u64;

// -------- device scratch (no allocation allowed) --------
__device__ __align__(16) float g_ssq[NROWS];
__device__ __align__(16) float g_u  [RR*NROWS];   // planar [r][row], pre-scaled by rmsnorm
__device__ __align__(16) float g_pu [NROWS*RR];   // row-major
__device__ __align__(16) float g_pw1[NROWS*RFF];  // row-major
__device__ __align__(16) float g_h  [RR*NROWS];   // planar [r][row]
__device__ __align__(16) float g_g  [NROWS*RFF];  // row-major
__device__ __align__(16) float g_Ut [RR*DD];      // U transposed (for k_main)
__device__ __align__(16) float g_Bhi[DD*NB];      // tf32 hi of B [k][n]
__device__ __align__(16) float g_Blo[DD*NB];      // tf32 lo of B [k][n]
__device__ float g_G[16];    // U^T U
__device__ float g_M[64];    // U^T (w*W1)
__device__ float g_a[RR];

// -------- packed f32x2 helpers --------
__device__ __forceinline__ u64 fma2(u64 a, u64 b, u64 c){
    u64 d; asm("fma.rn.f32x2 %0, %1, %2, %3;" : "=l"(d) : "l"(a), "l"(b), "l"(c)); return d;
}
__device__ __forceinline__ u64 add2(u64 a, u64 b){
    u64 d; asm("add.rn.f32x2 %0, %1, %2;" : "=l"(d) : "l"(a), "l"(b)); return d;
}
__device__ __forceinline__ u64 pack2(float x, float y){
    u64 r; asm("mov.b64 %0, {%1, %2};" : "=l"(r) : "f"(x), "f"(y)); return r;
}
__device__ __forceinline__ float warp_sum(float v){
    v += __shfl_down_sync(0xffffffffu, v, 16);
    v += __shfl_down_sync(0xffffffffu, v, 8);
    v += __shfl_down_sync(0xffffffffu, v, 4);
    v += __shfl_down_sync(0xffffffffu, v, 2);
    v += __shfl_down_sync(0xffffffffu, v, 1);
    return v;
}
__device__ __forceinline__ float gelu_tanh(float x){
    float c = 0.7978845608028654f * (x + 0.044715f * x * x * x);
    return 0.5f * x * (1.0f + tanhf(c));
}
// ---- tf32 helpers ----
__device__ __forceinline__ void hilo_tf32(float x, uint32_t& h, uint32_t& lo){
    asm("cvt.rna.tf32.f32 %0, %1;" : "=r"(h) : "f"(x));
    float hf = __uint_as_float(h);
    float lf = x - hf;
    asm("cvt.rna.tf32.f32 %0, %1;" : "=r"(lo) : "f"(lf));
}
__device__ __forceinline__ void mma_tf32(float* c, const uint32_t* a, uint32_t b0, uint32_t b1){
    asm("mma.sync.aligned.m16n8k8.row.col.f32.tf32.tf32.f32 "
        "{%0,%1,%2,%3},{%4,%5,%6,%7},{%8,%9},{%0,%1,%2,%3};"
        : "+f"(c[0]), "+f"(c[1]), "+f"(c[2]), "+f"(c[3])
        : "r"(a[0]), "r"(a[1]), "r"(a[2]), "r"(a[3]), "r"(b0), "r"(b1));
}

// ======================= prep kernels =======================
__global__ void k_prep_a(const float* __restrict__ a_logit){
    int tid = threadIdx.x;
    if (tid < RR) g_a[tid] = 1.0f / (1.0f + expf(-a_logit[tid]));
}

__global__ void k_prep_fold(const float* __restrict__ norm_w, const float* __restrict__ V,
                            const float* __restrict__ U, const float* __restrict__ W1){
    int d = blockIdx.x * 256 + threadIdx.x;
    float w = norm_w[d];
    #pragma unroll
    for (int r = 0; r < RR; r++)
        g_Ut[r*DD + d] = U[d*RR + r];
    // B hi/lo (tf32 split), layout [k=d][n]
    #pragma unroll
    for (int n = 0; n < NB; n++){
        float bv = (n < 4) ? w * V[d*RR + n]
                 : (n < 8) ? U[d*RR + (n-4)]
                           : w * W1[d*RFF + (n-8)];
        uint32_t h, lo;
        hilo_tf32(bv, h, lo);
        g_Bhi[(size_t)d*NB + n] = __uint_as_float(h);
        g_Blo[(size_t)d*NB + n] = __uint_as_float(lo);
    }
}

__global__ void k_prep_gm(const float* __restrict__ norm_w, const float* __restrict__ U,
                          const float* __restrict__ W1){
    int j = blockIdx.x;   // 0..79
    int tid = threadIdx.x;
    float s = 0.f;
    if (j < 16){
        int k = j >> 2, q = j & 3;
        for (int d = tid; d < DD; d += 256)
            s += U[d*RR + k] * U[d*RR + q];
    } else {
        int k = (j-16) >> 4, r = (j-16) & 15;
        for (int d = tid; d < DD; d += 256)
            s += U[d*RR + k] * norm_w[d] * W1[d*RFF + r];
    }
    s = warp_sum(s);
    __shared__ float sh[8];
    if ((tid & 31) == 0) sh[tid >> 5] = s;
    __syncthreads();
    if (tid == 0){
        float t = 0.f;
        #pragma unroll
        for (int i = 0; i < 8; i++) t += sh[i];
        if (j < 16) g_G[j] = t; else g_M[j-16] = t;
    }
}

// ======================= k_u_mma: [16384x2048]@[2048x24] via tf32 mma (3xTF32) =======================
// 128 threads = 4 warps; warp w owns m16 row tile -> 64 rows/block; grid 256.
// K staged in chunks of 32; ssq accumulated during staging.
__global__ void __launch_bounds__(128) k_u_mma(const float* __restrict__ x){
    const int tid = threadIdx.x;
    const int w = tid >> 5, l = tid & 31;
    const int row0 = blockIdx.x * 64;

    __shared__ float xs[64][36];        // x chunk, padded (bank = 4r+c, conflict-free frags)
    __shared__ float bh[32][25];        // B hi chunk [k][n], pad 25
    __shared__ float bl[32][25];        // B lo chunk
    __shared__ float sst[64][9];        // ssq partials
    __shared__ float sscale[64];

    float chh[3][4], cx[3][4];
    #pragma unroll
    for (int nt = 0; nt < 3; nt++)
        #pragma unroll
        for (int i = 0; i < 4; i++){ chh[nt][i] = 0.f; cx[nt][i] = 0.f; }

    float sacc[4] = {0.f, 0.f, 0.f, 0.f};
    const int subrow = tid >> 3;         // 0..15
    const int koff   = (tid & 7) * 4;    // 0..28

    for (int kc = 0; kc < DD/32; kc++){
        const int kbase = kc * 32;
        // ---- stage x (64 rows x 32 k) ----
        #pragma unroll
        for (int p = 0; p < 4; p++){
            int r = subrow + 16*p;
            float4 v = *reinterpret_cast<const float4*>(
                x + (size_t)(row0 + r)*DD + kbase + koff);
            *reinterpret_cast<float4*>(&xs[r][koff]) = v;
            sacc[p] += v.x*v.x + v.y*v.y + v.z*v.z + v.w*v.w;
        }
        // ---- stage B hi/lo (32 x 24) ----
        #pragma unroll
        for (int i = 0; i < 6; i++){
            int idx = tid + i*128;       // 0..767
            int kk = idx / NB, nn = idx % NB;
            bh[kk][nn] = g_Bhi[(size_t)(kbase+kk)*NB + nn];
            bl[kk][nn] = g_Blo[(size_t)(kbase+kk)*NB + nn];
        }
        __syncthreads();

        // ---- 4 k8 steps ----
        const int arow = (w << 4) + (l >> 2);
        #pragma unroll
        for (int s = 0; s < 4; s++){
            const int kk = s*8 + (l & 3);
            uint32_t ah[4], al[4];
            hilo_tf32(xs[arow  ][kk  ], ah[0], al[0]);
            hilo_tf32(xs[arow+8][kk  ], ah[1], al[1]);
            hilo_tf32(xs[arow  ][kk+4], ah[2], al[2]);
            hilo_tf32(xs[arow+8][kk+4], ah[3], al[3]);
            #pragma unroll
            for (int nt = 0; nt < 3; nt++){
                const int nn = nt*8 + (l >> 2);
                uint32_t b0h = __float_as_uint(bh[kk  ][nn]);
                uint32_t b1h = __float_as_uint(bh[kk+4 - (l&3) + (l&3)][nn]); // bh[kk+4][nn]
                b1h = __float_as_uint(bh[s*8 + (l&3) + 4][nn]);
                uint32_t b0l = __float_as_uint(bl[s*8 + (l&3)    ][nn]);
                uint32_t b1l = __float_as_uint(bl[s*8 + (l&3) + 4][nn]);
                mma_tf32(chh[nt], ah, b0h, b1h);
                mma_tf32(cx[nt],  ah, b0l, b1l);
                mma_tf32(cx[nt],  al, b0h, b1h);
            }
        }
        __syncthreads();
    }

    // ---- ssq reduce ----
    #pragma unroll
    for (int p = 0; p < 4; p++)
        sst[subrow + 16*p][tid & 7] = sacc[p];
    __syncthreads();
    if (tid < 64){
        float s = 0.f;
        #pragma unroll
        for (int i = 0; i < 8; i++) s += sst[tid][i];
        g_ssq[row0 + tid] = s;
        sscale[tid] = rsqrtf(s * (1.0f/DD) + EPS);
    }
    __syncthreads();

    // ---- epilogue: scatter C frags to planes ----
    const int rbase = (w << 4) + (l >> 2);
    #pragma unroll
    for (int nt = 0; nt < 3; nt++){
        #pragma unroll
        for (int reg = 0; reg < 4; reg++){
            int rr = rbase + ((reg >> 1) << 3);
            int n  = nt*8 + 2*(l & 3) + (reg & 1);
            int grow = row0 + rr;
            float val = chh[nt][reg] + cx[nt][reg];
            if (n < 4)      g_u[n*NROWS + grow] = val * sscale[rr];
            else if (n < 8) g_pu[(size_t)grow*RR + (n-4)] = val;
            else            g_pw1[(size_t)grow*RFF + (n-8)] = val;
        }
    }
}

// ======================= k_scan: warp-parallel linear-recurrence scan =======================
__global__ void __launch_bounds__(256) k_scan(){
    const int b = blockIdx.x >> 2;
    const int r = blockIdx.x & 3;
    const float a = g_a[r];
    const int tid = threadIdx.x, l = tid & 31, w = tid >> 5;
    const float* u = g_u + r*NROWS + b*SS;

    float uu[16];
    float4* uu4 = reinterpret_cast<float4*>(uu);
    #pragma unroll
    for (int i = 0; i < 4; i++)
        uu4[i] = reinterpret_cast<const float4*>(u)[tid*4 + i];

    float f = 0.f;
    #pragma unroll
    for (int i = 0; i < 16; i++) f = a*f + uu[i];

    float A = a; A *= A; A *= A; A *= A; A *= A;   // a^16

    float I = f, As = A;
    #pragma unroll
    for (int st = 0; st < 5; st++){
        float gg = __shfl_up_sync(0xffffffffu, I, 1 << st);
        if (l >= (1 << st)) I += As * gg;
        As *= As;
    }

    __shared__ float Tw[8], Ww[8];
    if (l == 31) Tw[w] = I;
    __syncthreads();
    if (tid == 0){
        float A32 = A;
        #pragma unroll
        for (int k = 0; k < 5; k++) A32 *= A32;  // a^512
        float c = 0.f;
        #pragma unroll
        for (int j = 0; j < 8; j++){ Ww[j] = c; c = A32*c + Tw[j]; }
    }
    __syncthreads();

    float Al = 1.f, p = A;
    #pragma unroll
    for (int bit = 0; bit < 5; bit++){ if ((l >> bit) & 1) Al *= p; p *= p; }
    float Iprev = __shfl_up_sync(0xffffffffu, I, 1);
    float c = ((l == 0) ? 0.f : Iprev) + Al * Ww[w];

    float* hh = g_h + r*NROWS + b*SS;
    float h = c;
    float ho[16];
    #pragma unroll
    for (int i = 0; i < 16; i++){ h = a*h + uu[i]; ho[i] = h; }
    float4* ho4 = reinterpret_cast<float4*>(ho);
    #pragma unroll
    for (int i = 0; i < 4; i++)
        reinterpret_cast<float4*>(hh)[tid*4 + i] = ho4[i];
}

// ======================= k_post: per-row scale1, t, gelu =======================
__global__ void __launch_bounds__(256) k_post(){
    __shared__ float sG[16], sM[64];
    int tid = threadIdx.x;
    if (tid < 16) sG[tid] = g_G[tid];
    if (tid < 64) sM[tid] = g_M[tid];
    __syncthreads();

    int row = blockIdx.x * 256 + tid;
    float h[4], p[4];
    #pragma unroll
    for (int k = 0; k < 4; k++) h[k] = g_h[k*NROWS + row];
    float4 p4 = reinterpret_cast<const float4*>(g_pu)[row];
    p[0]=p4.x; p[1]=p4.y; p[2]=p4.z; p[3]=p4.w;

    float s1 = g_ssq[row];
    #pragma unroll
    for (int k = 0; k < 4; k++) s1 += 2.0f * h[k] * p[k];
    #pragma unroll
    for (int k = 0; k < 4; k++)
        #pragma unroll
        for (int q = 0; q < 4; q++) s1 += h[k] * h[q] * sG[k*4+q];
    float scale = rsqrtf(s1 * (1.0f/DD) + EPS);

    #pragma unroll
    for (int r = 0; r < RFF; r++){
        float t = g_pw1[(size_t)row*RFF + r];
        #pragma unroll
        for (int k = 0; k < 4; k++) t += h[k] * sM[k*16 + r];
        g_g[(size_t)row*RFF + r] = gelu_tanh(t * scale);
    }
}

// ======================= k_main: out = x + U h + g @ W2 (R12 exact) =======================
__global__ void __launch_bounds__(256, 2) k_main(const float* __restrict__ x,
                                                 const float* __restrict__ W2,
                                                 float* __restrict__ out){
    const int row0 = blockIdx.x * TRM;
    const int tid  = threadIdx.x;
    const int q    = blockIdx.y * 256 + tid;

    ulonglong2 ut[4], w2[16];
    #pragma unroll
    for (int k = 0; k < 4; k++)
        ut[k] = reinterpret_cast<const ulonglong2*>(g_Ut)[k*(DD/4) + q];
    #pragma unroll
    for (int r = 0; r < RFF; r++)
        w2[r] = reinterpret_cast<const ulonglong2*>(W2)[r*(DD/4) + q];

    __shared__ __align__(16) float hs[TRM][20];
    for (int i = tid; i < TRM*20; i += 256){
        int row = i / 20, j = i % 20;
        hs[row][j] = (j < 4) ? g_h[j*NROWS + row0 + row]
                             : g_g[(size_t)(row0+row)*RFF + (j-4)];
    }
    __syncthreads();

    const ulonglong2* xr = reinterpret_cast<const ulonglong2*>(x) + (size_t)row0*(DD/4) + q;
    ulonglong2*       op = reinterpret_cast<ulonglong2*>(out)     + (size_t)row0*(DD/4) + q;

    ulonglong2 xa = xr[0];
    #pragma unroll
    for (int row = 0; row < TRM; row++){
        ulonglong2 xn = xa;
        if (row + 1 < TRM) xn = xr[(size_t)(row+1)*(DD/4)];

        float sc[20];
        float4* sc4 = reinterpret_cast<float4*>(sc);
        const float4* hp = reinterpret_cast<const float4*>(&hs[row][0]);
        #pragma unroll
        for (int i = 0; i < 5; i++) sc4[i] = hp[i];

        u64 a0 = xa.x, a1 = xa.y, b0 = 0ull, b1 = 0ull;
        #pragma unroll
        for (int k = 0; k < 4; k++){
            u64 s = pack2(sc[k], sc[k]);
            if (k & 1){ b0 = fma2(s, ut[k].x, b0); b1 = fma2(s, ut[k].y, b1); }
            else      { a0 = fma2(s, ut[k].x, a0); a1 = fma2(s, ut[k].y, a1); }
        }
        #pragma unroll
        for (int r = 0; r < RFF; r++){
            u64 s = pack2(sc[4+r], sc[4+r]);
            if (r & 1){ b0 = fma2(s, w2[r].x, b0); b1 = fma2(s, w2[r].y, b1); }
            else      { a0 = fma2(s, w2[r].x, a0); a1 = fma2(s, w2[r].y, a1); }
        }
        ulonglong2 o;
        o.x = add2(a0, b0);
        o.y = add2(a1, b1);
        op[(size_t)row*(DD/4)] = o;
        xa = xn;
    }
}

// ======================= launch =======================
extern "C" void kernel_launch(void* const* d_in, const int* in_sizes, int n_in,
                              void* d_out, int out_size){
    const float* x       = (const float*)d_in[0];
    const float* norm_w  = (const float*)d_in[1];
    const float* V       = (const float*)d_in[2];
    const float* U       = (const float*)d_in[3];
    const float* a_logit = (const float*)d_in[4];
    const float* W1      = (const float*)d_in[5];
    const float* W2      = (const float*)d_in[6];
    float* out = (float*)d_out;

    k_prep_a   <<<1, 32>>>(a_logit);                 // launch 0
    k_prep_fold<<<8, 256>>>(norm_w, V, U, W1);       // launch 1
    k_prep_gm  <<<80, 256>>>(norm_w, U, W1);         // launch 2
    k_u_mma    <<<NROWS/64, 128>>>(x);               // launch 3  (profiled)
    k_scan     <<<BB*RR, 256>>>();                   // launch 4
    k_post     <<<NROWS/256, 256>>>();               // launch 5
    dim3 gm(NROWS/TRM, 2);
    k_main     <<<gm, 256>>>(x, W2, out);            // launch 6
}

// round 17
// speedup vs baseline: 1.4515x; 1.4515x over previous
#include <cuda_runtime.h>
#include <cstdint>

#define BB 4
#define SS 4096
#define DD 2048
#define RR 4
#define RFF 16
#define NROWS (BB*SS)   // 16384
#define TRM 16          // rows per block in k_main
#define EPS 1e-6f
#define NB 24           // B columns: 0..3 wV, 4..7 U, 8..23 wW1
#define KSPLIT 4
#define KCH (DD/32/KSPLIT)   // 16 k-chunks of 32 per split

typedef unsigned long long u64;

// -------- device scratch (no allocation allowed) --------
__device__ __align__(16) float g_part[KSPLIT*25*NROWS];  // partial planes per K-split
__device__ __align__(16) float g_ssq[NROWS];
__device__ __align__(16) float g_u  [RR*NROWS];   // planar [r][row], pre-scaled by rmsnorm
__device__ __align__(16) float g_pu [NROWS*RR];   // row-major
__device__ __align__(16) float g_pw1[NROWS*RFF];  // row-major
__device__ __align__(16) float g_h  [RR*NROWS];   // planar [r][row]
__device__ __align__(16) float g_g  [NROWS*RFF];  // row-major
__device__ __align__(16) float g_Ut [RR*DD];      // U transposed (for k_main)
__device__ __align__(16) float g_Bhi[DD*NB];      // tf32 hi of B [k][n]
__device__ __align__(16) float g_Blo[DD*NB];      // tf32 lo of B [k][n]
__device__ float g_G[16];    // U^T U
__device__ float g_M[64];    // U^T (w*W1)
__device__ float g_a[RR];

// -------- packed f32x2 helpers --------
__device__ __forceinline__ u64 fma2(u64 a, u64 b, u64 c){
    u64 d; asm("fma.rn.f32x2 %0, %1, %2, %3;" : "=l"(d) : "l"(a), "l"(b), "l"(c)); return d;
}
__device__ __forceinline__ u64 add2(u64 a, u64 b){
    u64 d; asm("add.rn.f32x2 %0, %1, %2;" : "=l"(d) : "l"(a), "l"(b)); return d;
}
__device__ __forceinline__ u64 pack2(float x, float y){
    u64 r; asm("mov.b64 %0, {%1, %2};" : "=l"(r) : "f"(x), "f"(y)); return r;
}
__device__ __forceinline__ float warp_sum(float v){
    v += __shfl_down_sync(0xffffffffu, v, 16);
    v += __shfl_down_sync(0xffffffffu, v, 8);
    v += __shfl_down_sync(0xffffffffu, v, 4);
    v += __shfl_down_sync(0xffffffffu, v, 2);
    v += __shfl_down_sync(0xffffffffu, v, 1);
    return v;
}
__device__ __forceinline__ float gelu_tanh(float x){
    float c = 0.7978845608028654f * (x + 0.044715f * x * x * x);
    return 0.5f * x * (1.0f + tanhf(c));
}
// ---- tf32 helpers ----
__device__ __forceinline__ void hilo_tf32(float x, uint32_t& h, uint32_t& lo){
    asm("cvt.rna.tf32.f32 %0, %1;" : "=r"(h) : "f"(x));
    float hf = __uint_as_float(h);
    float lf = x - hf;
    asm("cvt.rna.tf32.f32 %0, %1;" : "=r"(lo) : "f"(lf));
}
__device__ __forceinline__ void mma_tf32(float* c, const uint32_t* a, uint32_t b0, uint32_t b1){
    asm("mma.sync.aligned.m16n8k8.row.col.f32.tf32.tf32.f32 "
        "{%0,%1,%2,%3},{%4,%5,%6,%7},{%8,%9},{%0,%1,%2,%3};"
        : "+f"(c[0]), "+f"(c[1]), "+f"(c[2]), "+f"(c[3])
        : "r"(a[0]), "r"(a[1]), "r"(a[2]), "r"(a[3]), "r"(b0), "r"(b1));
}

// ======================= prep kernels =======================
__global__ void k_prep_a(const float* __restrict__ a_logit){
    int tid = threadIdx.x;
    if (tid < RR) g_a[tid] = 1.0f / (1.0f + expf(-a_logit[tid]));
}

__global__ void k_prep_fold(const float* __restrict__ norm_w, const float* __restrict__ V,
                            const float* __restrict__ U, const float* __restrict__ W1){
    int d = blockIdx.x * 256 + threadIdx.x;
    float w = norm_w[d];
    #pragma unroll
    for (int r = 0; r < RR; r++)
        g_Ut[r*DD + d] = U[d*RR + r];
    #pragma unroll
    for (int n = 0; n < NB; n++){
        float bv = (n < 4) ? w * V[d*RR + n]
                 : (n < 8) ? U[d*RR + (n-4)]
                           : w * W1[d*RFF + (n-8)];
        uint32_t h, lo;
        hilo_tf32(bv, h, lo);
        g_Bhi[(size_t)d*NB + n] = __uint_as_float(h);
        g_Blo[(size_t)d*NB + n] = __uint_as_float(lo);
    }
}

__global__ void k_prep_gm(const float* __restrict__ norm_w, const float* __restrict__ U,
                          const float* __restrict__ W1){
    int j = blockIdx.x;   // 0..79
    int tid = threadIdx.x;
    float s = 0.f;
    if (j < 16){
        int k = j >> 2, q = j & 3;
        for (int d = tid; d < DD; d += 256)
            s += U[d*RR + k] * U[d*RR + q];
    } else {
        int k = (j-16) >> 4, r = (j-16) & 15;
        for (int d = tid; d < DD; d += 256)
            s += U[d*RR + k] * norm_w[d] * W1[d*RFF + r];
    }
    s = warp_sum(s);
    __shared__ float sh[8];
    if ((tid & 31) == 0) sh[tid >> 5] = s;
    __syncthreads();
    if (tid == 0){
        float t = 0.f;
        #pragma unroll
        for (int i = 0; i < 8; i++) t += sh[i];
        if (j < 16) g_G[j] = t; else g_M[j-16] = t;
    }
}

// ======================= k_u_mma: split-K tf32 mma GEMM =======================
// grid (256, 4): blockIdx.x = 64-row tile, blockIdx.y = K-split (512 k each).
// 128 threads = 4 warps, warp w owns m16 row tile. Writes 25 partial planes.
__global__ void __launch_bounds__(128) k_u_mma(const float* __restrict__ x){
    const int tid = threadIdx.x;
    const int w = tid >> 5, l = tid & 31;
    const int row0 = blockIdx.x * 64;
    const int ks   = blockIdx.y;

    __shared__ float xs[64][36];
    __shared__ float bh[32][25];
    __shared__ float bl[32][25];
    __shared__ float sst[64][9];

    float chh[3][4], cx[3][4];
    #pragma unroll
    for (int nt = 0; nt < 3; nt++)
        #pragma unroll
        for (int i = 0; i < 4; i++){ chh[nt][i] = 0.f; cx[nt][i] = 0.f; }

    float sacc[4] = {0.f, 0.f, 0.f, 0.f};
    const int subrow = tid >> 3;
    const int koff   = (tid & 7) * 4;

    for (int kc = ks*KCH; kc < (ks+1)*KCH; kc++){
        const int kbase = kc * 32;
        // ---- stage x (64 rows x 32 k) ----
        #pragma unroll
        for (int p = 0; p < 4; p++){
            int r = subrow + 16*p;
            float4 v = *reinterpret_cast<const float4*>(
                x + (size_t)(row0 + r)*DD + kbase + koff);
            *reinterpret_cast<float4*>(&xs[r][koff]) = v;
            sacc[p] += v.x*v.x + v.y*v.y + v.z*v.z + v.w*v.w;
        }
        // ---- stage B hi/lo (32 x 24) ----
        #pragma unroll
        for (int i = 0; i < 6; i++){
            int idx = tid + i*128;
            int kk = idx / NB, nn = idx % NB;
            bh[kk][nn] = g_Bhi[(size_t)(kbase+kk)*NB + nn];
            bl[kk][nn] = g_Blo[(size_t)(kbase+kk)*NB + nn];
        }
        __syncthreads();

        // ---- 4 k8 steps ----
        const int arow = (w << 4) + (l >> 2);
        #pragma unroll
        for (int s = 0; s < 4; s++){
            const int kk = s*8 + (l & 3);
            uint32_t ah[4], al[4];
            hilo_tf32(xs[arow  ][kk  ], ah[0], al[0]);
            hilo_tf32(xs[arow+8][kk  ], ah[1], al[1]);
            hilo_tf32(xs[arow  ][kk+4], ah[2], al[2]);
            hilo_tf32(xs[arow+8][kk+4], ah[3], al[3]);
            #pragma unroll
            for (int nt = 0; nt < 3; nt++){
                const int nn = nt*8 + (l >> 2);
                uint32_t b0h = __float_as_uint(bh[kk    ][nn]);
                uint32_t b1h = __float_as_uint(bh[kk + 4][nn]);
                uint32_t b0l = __float_as_uint(bl[kk    ][nn]);
                uint32_t b1l = __float_as_uint(bl[kk + 4][nn]);
                mma_tf32(chh[nt], ah, b0h, b1h);
                mma_tf32(cx[nt],  ah, b0l, b1l);
                mma_tf32(cx[nt],  al, b0h, b1h);
            }
        }
        __syncthreads();
    }

    // ---- ssq partial reduce ----
    #pragma unroll
    for (int p = 0; p < 4; p++)
        sst[subrow + 16*p][tid & 7] = sacc[p];
    __syncthreads();
    if (tid < 64){
        float s = 0.f;
        #pragma unroll
        for (int i = 0; i < 8; i++) s += sst[tid][i];
        g_part[((size_t)ks*25 + 0)*NROWS + row0 + tid] = s;
    }

    // ---- epilogue: scatter C frags to partial planes (no scaling) ----
    float* base = g_part + (size_t)ks*25*NROWS;
    const int rbase = (w << 4) + (l >> 2);
    #pragma unroll
    for (int nt = 0; nt < 3; nt++){
        #pragma unroll
        for (int reg = 0; reg < 4; reg++){
            int rr = rbase + ((reg >> 1) << 3);
            int n  = nt*8 + 2*(l & 3) + (reg & 1);
            float val = chh[nt][reg] + cx[nt][reg];
            base[(size_t)(1+n)*NROWS + row0 + rr] = val;
        }
    }
}

// ======================= k_reduce: sum K-split partials, emit final layouts =======================
__global__ void __launch_bounds__(256) k_reduce(){
    int row = blockIdx.x * 256 + threadIdx.x;

    float ssq = 0.f;
    #pragma unroll
    for (int ks = 0; ks < KSPLIT; ks++)
        ssq += g_part[((size_t)ks*25 + 0)*NROWS + row];
    g_ssq[row] = ssq;
    float scale = rsqrtf(ssq * (1.0f/DD) + EPS);

    #pragma unroll
    for (int n = 0; n < 4; n++){
        float v = 0.f;
        #pragma unroll
        for (int ks = 0; ks < KSPLIT; ks++)
            v += g_part[((size_t)ks*25 + 1 + n)*NROWS + row];
        g_u[n*NROWS + row] = v * scale;
    }
    float pu[4];
    #pragma unroll
    for (int n = 0; n < 4; n++){
        float v = 0.f;
        #pragma unroll
        for (int ks = 0; ks < KSPLIT; ks++)
            v += g_part[((size_t)ks*25 + 5 + n)*NROWS + row];
        pu[n] = v;
    }
    *reinterpret_cast<float4*>(g_pu + (size_t)row*RR) = *reinterpret_cast<float4*>(pu);

    float pw[16];
    #pragma unroll
    for (int n = 0; n < 16; n++){
        float v = 0.f;
        #pragma unroll
        for (int ks = 0; ks < KSPLIT; ks++)
            v += g_part[((size_t)ks*25 + 9 + n)*NROWS + row];
        pw[n] = v;
    }
    #pragma unroll
    for (int i = 0; i < 4; i++)
        reinterpret_cast<float4*>(g_pw1 + (size_t)row*RFF)[i] =
            reinterpret_cast<float4*>(pw)[i];
}

// ======================= k_scan: warp-parallel linear-recurrence scan =======================
__global__ void __launch_bounds__(256) k_scan(){
    const int b = blockIdx.x >> 2;
    const int r = blockIdx.x & 3;
    const float a = g_a[r];
    const int tid = threadIdx.x, l = tid & 31, w = tid >> 5;
    const float* u = g_u + r*NROWS + b*SS;

    float uu[16];
    float4* uu4 = reinterpret_cast<float4*>(uu);
    #pragma unroll
    for (int i = 0; i < 4; i++)
        uu4[i] = reinterpret_cast<const float4*>(u)[tid*4 + i];

    float f = 0.f;
    #pragma unroll
    for (int i = 0; i < 16; i++) f = a*f + uu[i];

    float A = a; A *= A; A *= A; A *= A; A *= A;   // a^16

    float I = f, As = A;
    #pragma unroll
    for (int st = 0; st < 5; st++){
        float gg = __shfl_up_sync(0xffffffffu, I, 1 << st);
        if (l >= (1 << st)) I += As * gg;
        As *= As;
    }

    __shared__ float Tw[8], Ww[8];
    if (l == 31) Tw[w] = I;
    __syncthreads();
    if (tid == 0){
        float A32 = A;
        #pragma unroll
        for (int k = 0; k < 5; k++) A32 *= A32;  // a^512
        float c = 0.f;
        #pragma unroll
        for (int j = 0; j < 8; j++){ Ww[j] = c; c = A32*c + Tw[j]; }
    }
    __syncthreads();

    float Al = 1.f, p = A;
    #pragma unroll
    for (int bit = 0; bit < 5; bit++){ if ((l >> bit) & 1) Al *= p; p *= p; }
    float Iprev = __shfl_up_sync(0xffffffffu, I, 1);
    float c = ((l == 0) ? 0.f : Iprev) + Al * Ww[w];

    float* hh = g_h + r*NROWS + b*SS;
    float h = c;
    float ho[16];
    #pragma unroll
    for (int i = 0; i < 16; i++){ h = a*h + uu[i]; ho[i] = h; }
    float4* ho4 = reinterpret_cast<float4*>(ho);
    #pragma unroll
    for (int i = 0; i < 4; i++)
        reinterpret_cast<float4*>(hh)[tid*4 + i] = ho4[i];
}

// ======================= k_post: per-row scale1, t, gelu =======================
__global__ void __launch_bounds__(256) k_post(){
    __shared__ float sG[16], sM[64];
    int tid = threadIdx.x;
    if (tid < 16) sG[tid] = g_G[tid];
    if (tid < 64) sM[tid] = g_M[tid];
    __syncthreads();

    int row = blockIdx.x * 256 + tid;
    float h[4], p[4];
    #pragma unroll
    for (int k = 0; k < 4; k++) h[k] = g_h[k*NROWS + row];
    float4 p4 = reinterpret_cast<const float4*>(g_pu)[row];
    p[0]=p4.x; p[1]=p4.y; p[2]=p4.z; p[3]=p4.w;

    float s1 = g_ssq[row];
    #pragma unroll
    for (int k = 0; k < 4; k++) s1 += 2.0f * h[k] * p[k];
    #pragma unroll
    for (int k = 0; k < 4; k++)
        #pragma unroll
        for (int q = 0; q < 4; q++) s1 += h[k] * h[q] * sG[k*4+q];
    float scale = rsqrtf(s1 * (1.0f/DD) + EPS);

    #pragma unroll
    for (int r = 0; r < RFF; r++){
        float t = g_pw1[(size_t)row*RFF + r];
        #pragma unroll
        for (int k = 0; k < 4; k++) t += h[k] * sM[k*16 + r];
        g_g[(size_t)row*RFF + r] = gelu_tanh(t * scale);
    }
}

// ======================= k_main: out = x + U h + g @ W2 (R12 exact) =======================
__global__ void __launch_bounds__(256, 2) k_main(const float* __restrict__ x,
                                                 const float* __restrict__ W2,
                                                 float* __restrict__ out){
    const int row0 = blockIdx.x * TRM;
    const int tid  = threadIdx.x;
    const int q    = blockIdx.y * 256 + tid;

    ulonglong2 ut[4], w2[16];
    #pragma unroll
    for (int k = 0; k < 4; k++)
        ut[k] = reinterpret_cast<const ulonglong2*>(g_Ut)[k*(DD/4) + q];
    #pragma unroll
    for (int r = 0; r < RFF; r++)
        w2[r] = reinterpret_cast<const ulonglong2*>(W2)[r*(DD/4) + q];

    __shared__ __align__(16) float hs[TRM][20];
    for (int i = tid; i < TRM*20; i += 256){
        int row = i / 20, j = i % 20;
        hs[row][j] = (j < 4) ? g_h[j*NROWS + row0 + row]
                             : g_g[(size_t)(row0+row)*RFF + (j-4)];
    }
    __syncthreads();

    const ulonglong2* xr = reinterpret_cast<const ulonglong2*>(x) + (size_t)row0*(DD/4) + q;
    ulonglong2*       op = reinterpret_cast<ulonglong2*>(out)     + (size_t)row0*(DD/4) + q;

    ulonglong2 xa = xr[0];
    #pragma unroll
    for (int row = 0; row < TRM; row++){
        ulonglong2 xn = xa;
        if (row + 1 < TRM) xn = xr[(size_t)(row+1)*(DD/4)];

        float sc[20];
        float4* sc4 = reinterpret_cast<float4*>(sc);
        const float4* hp = reinterpret_cast<const float4*>(&hs[row][0]);
        #pragma unroll
        for (int i = 0; i < 5; i++) sc4[i] = hp[i];

        u64 a0 = xa.x, a1 = xa.y, b0 = 0ull, b1 = 0ull;
        #pragma unroll
        for (int k = 0; k < 4; k++){
            u64 s = pack2(sc[k], sc[k]);
            if (k & 1){ b0 = fma2(s, ut[k].x, b0); b1 = fma2(s, ut[k].y, b1); }
            else      { a0 = fma2(s, ut[k].x, a0); a1 = fma2(s, ut[k].y, a1); }
        }
        #pragma unroll
        for (int r = 0; r < RFF; r++){
            u64 s = pack2(sc[4+r], sc[4+r]);
            if (r & 1){ b0 = fma2(s, w2[r].x, b0); b1 = fma2(s, w2[r].y, b1); }
            else      { a0 = fma2(s, w2[r].x, a0); a1 = fma2(s, w2[r].y, a1); }
        }
        ulonglong2 o;
        o.x = add2(a0, b0);
        o.y = add2(a1, b1);
        op[(size_t)row*(DD/4)] = o;
        xa = xn;
    }
}

// ======================= launch =======================
extern "C" void kernel_launch(void* const* d_in, const int* in_sizes, int n_in,
                              void* d_out, int out_size){
    const float* x       = (const float*)d_in[0];
    const float* norm_w  = (const float*)d_in[1];
    const float* V       = (const float*)d_in[2];
    const float* U       = (const float*)d_in[3];
    const float* a_logit = (const float*)d_in[4];
    const float* W1      = (const float*)d_in[5];
    const float* W2      = (const float*)d_in[6];
    float* out = (float*)d_out;

    k_prep_a   <<<1, 32>>>(a_logit);                 // launch 0
    k_prep_fold<<<8, 256>>>(norm_w, V, U, W1);       // launch 1
    k_prep_gm  <<<80, 256>>>(norm_w, U, W1);         // launch 2
    dim3 gu(NROWS/64, KSPLIT);
    k_u_mma    <<<gu, 128>>>(x);                     // launch 3  (profiled)
    k_reduce   <<<NROWS/256, 256>>>();               // launch 4
    k_scan     <<<BB*RR, 256>>>();                   // launch 5
    k_post     <<<NROWS/256, 256>>>();               // launch 6
    dim3 gm(NROWS/TRM, 2);
    k_main     <<<gm, 256>>>(x, W2, out);            // launch 7
}